// round 1
// baseline (speedup 1.0000x reference)
#include <cuda_runtime.h>
#include <float.h>
#include <math.h>

#define BATCH   1024
#define DIM     384
#define NCUBES  131072
#define TOPK    16

#define BT      64            // queries per CTA tile
#define CT      64            // cubes per n-tile
#define KT      32            // k tile
#define NCHUNK  2048          // cubes per CTA (chunk)
#define NTILES  (NCHUNK/CT)   // 32
#define NCHUNKS (NCUBES/NCHUNK) // 64
#define BTILES  (BATCH/BT)    // 16

// ---------------- device scratch (no dynamic allocation allowed) ----------------
__device__ float g_qn[BATCH * DIM];                       // normalized queries
__device__ float g_cand_v[BATCH * NCHUNKS * TOPK];        // per-chunk top-16 vals
__device__ int   g_cand_i[BATCH * NCHUNKS * TOPK];        // per-chunk top-16 idx

// ---------------- kernel 1: normalize queries ----------------
__global__ __launch_bounds__(128) void norm_q_kernel(const float* __restrict__ q) {
    int b = blockIdx.x;
    const float* row = q + b * DIM;
    float s = 0.f;
    for (int i = threadIdx.x; i < DIM; i += 128) { float v = row[i]; s += v * v; }
    __shared__ float red[4];
    #pragma unroll
    for (int o = 16; o; o >>= 1) s += __shfl_xor_sync(0xffffffffu, s, o);
    if ((threadIdx.x & 31) == 0) red[threadIdx.x >> 5] = s;
    __syncthreads();
    if (threadIdx.x == 0) {
        float t = red[0] + red[1] + red[2] + red[3];
        red[0] = 1.0f / fmaxf(sqrtf(t), 1e-12f);
    }
    __syncthreads();
    float sc = red[0];
    for (int i = threadIdx.x; i < DIM; i += 128) g_qn[b * DIM + i] = row[i] * sc;
}

// ---------------- kernel 2: scores + fused per-chunk top-16 ----------------
// grid = (BTILES, NCHUNKS), block = 256
__global__ __launch_bounds__(256) void score_kernel(const float* __restrict__ emb,
                                                    const float* __restrict__ dual) {
    __shared__ union {
        struct {
            float Qs[KT][BT];   // k-major
            float Es[KT][CT];
            float Ds[KT][CT];
        } t;
        float sc[CT][BT + 4];   // [cube][query], padded row (68 floats)
    } sm;
    __shared__ float lv[BT][TOPK];   // ascending insertion lists (lv[.][0] = min)
    __shared__ int   li[BT][TOPK];

    const int btile = blockIdx.x;
    const int chunk = blockIdx.y;
    const int qbase = btile * BT;
    const int nbase = chunk * NCHUNK;
    const int tid   = threadIdx.x;
    const int tq    = tid >> 4;     // 0..15
    const int tc    = tid & 15;     // 0..15
    const int q0    = tq * 4;
    const int c0    = tc * 4;

    if (tid < BT) {
        #pragma unroll
        for (int k = 0; k < TOPK; k++) { lv[tid][k] = -FLT_MAX; li[tid][k] = 0; }
    }

    for (int nt = 0; nt < NTILES; nt++) {
        const int cbase = nbase + nt * CT;
        float accE[4][4], accD[4][4];
        #pragma unroll
        for (int i = 0; i < 4; i++)
            #pragma unroll
            for (int j = 0; j < 4; j++) { accE[i][j] = 0.f; accD[i][j] = 0.f; }

        for (int kt = 0; kt < DIM; kt += KT) {
            __syncthreads();   // previous consumers (compute reads / topk scan) done
            // load Q tile: 64 rows x 8 float4
            for (int l = tid; l < BT * 8; l += 256) {
                int r = l >> 3, c4 = l & 7;
                float4 v = *(const float4*)&g_qn[(qbase + r) * DIM + kt + c4 * 4];
                sm.t.Qs[c4 * 4 + 0][r] = v.x;
                sm.t.Qs[c4 * 4 + 1][r] = v.y;
                sm.t.Qs[c4 * 4 + 2][r] = v.z;
                sm.t.Qs[c4 * 4 + 3][r] = v.w;
            }
            // load E + D tiles: 64 rows x 8 float4 each
            for (int l = tid; l < CT * 8; l += 256) {
                int r = l >> 3, c4 = l & 7;
                int goff = (cbase + r) * DIM + kt + c4 * 4;
                float4 v = *(const float4*)&emb[goff];
                sm.t.Es[c4 * 4 + 0][r] = v.x;
                sm.t.Es[c4 * 4 + 1][r] = v.y;
                sm.t.Es[c4 * 4 + 2][r] = v.z;
                sm.t.Es[c4 * 4 + 3][r] = v.w;
                float4 w = *(const float4*)&dual[goff];
                sm.t.Ds[c4 * 4 + 0][r] = w.x;
                sm.t.Ds[c4 * 4 + 1][r] = w.y;
                sm.t.Ds[c4 * 4 + 2][r] = w.z;
                sm.t.Ds[c4 * 4 + 3][r] = w.w;
            }
            __syncthreads();

            #pragma unroll 8
            for (int kk = 0; kk < KT; kk++) {
                float4 qv = *(const float4*)&sm.t.Qs[kk][q0];
                float4 ev = *(const float4*)&sm.t.Es[kk][c0];
                float4 dv = *(const float4*)&sm.t.Ds[kk][c0];
                float qa[4] = {qv.x, qv.y, qv.z, qv.w};
                float ea[4] = {ev.x, ev.y, ev.z, ev.w};
                float da[4] = {dv.x, dv.y, dv.z, dv.w};
                #pragma unroll
                for (int i = 0; i < 4; i++) {
                    #pragma unroll
                    for (int j = 0; j < 4; j++) {
                        accE[i][j] = fmaf(qa[i], ea[j], accE[i][j]);
                        accD[i][j] = fmaf(qa[i], da[j], accD[i][j]);
                    }
                }
            }
        }

        __syncthreads();   // compute reads of sm.t done; now write scores into union
        #pragma unroll
        for (int j = 0; j < 4; j++) {
            float4 s;
            s.x = accE[0][j] + 0.35f * fmaxf(accD[0][j], 0.f);
            s.y = accE[1][j] + 0.35f * fmaxf(accD[1][j], 0.f);
            s.z = accE[2][j] + 0.35f * fmaxf(accD[2][j], 0.f);
            s.w = accE[3][j] + 0.35f * fmaxf(accD[3][j], 0.f);
            *(float4*)&sm.sc[c0 + j][q0] = s;
        }
        __syncthreads();

        // per-query top-16 update (one thread per query; conflict-free reads)
        if (tid < BT) {
            float* mylv = lv[tid];
            int*   myli = li[tid];
            float  thr  = mylv[0];
            for (int c = 0; c < CT; c++) {
                float s = sm.sc[c][tid];
                if (s > thr) {
                    int j = 0;
                    while (j < TOPK - 1 && mylv[j + 1] < s) {
                        mylv[j] = mylv[j + 1];
                        myli[j] = myli[j + 1];
                        j++;
                    }
                    mylv[j] = s;
                    myli[j] = cbase + c;
                    thr = mylv[0];
                }
            }
        }
        // next nt's first kt-loop __syncthreads() separates scan from tile loads
    }

    __syncthreads();
    if (tid < BT) {
        int q = qbase + tid;
        int base = (q * NCHUNKS + chunk) * TOPK;
        #pragma unroll
        for (int k = 0; k < TOPK; k++) {
            g_cand_v[base + k] = lv[tid][TOPK - 1 - k];
            g_cand_i[base + k] = li[tid][TOPK - 1 - k];
        }
    }
}

// ---------------- kernel 3: merge 64*16 candidates -> global top-16 ----------------
__global__ __launch_bounds__(256) void merge_kernel(float* __restrict__ out, int out_size) {
    const int q = blockIdx.x;
    const int tid = threadIdx.x;
    const int NC = NCHUNKS * TOPK;   // 1024
    __shared__ float v[NCHUNKS * TOPK];
    __shared__ int   id[NCHUNKS * TOPK];
    __shared__ float bwv[8];
    __shared__ int   bwi[8];
    __shared__ int   bws[8];

    for (int l = tid; l < NC; l += 256) {
        v[l]  = g_cand_v[q * NC + l];
        id[l] = g_cand_i[q * NC + l];
    }
    __syncthreads();

    for (int k = 0; k < TOPK; k++) {
        float bv = -FLT_MAX;
        int   bi = 0x7fffffff;
        int   bs = 0;
        for (int l = tid; l < NC; l += 256) {
            float vv = v[l];
            int   ii = id[l];
            if (vv > bv || (vv == bv && ii < bi)) { bv = vv; bi = ii; bs = l; }
        }
        #pragma unroll
        for (int o = 16; o; o >>= 1) {
            float ov = __shfl_xor_sync(0xffffffffu, bv, o);
            int   oi = __shfl_xor_sync(0xffffffffu, bi, o);
            int   os = __shfl_xor_sync(0xffffffffu, bs, o);
            if (ov > bv || (ov == bv && oi < bi)) { bv = ov; bi = oi; bs = os; }
        }
        if ((tid & 31) == 0) { bwv[tid >> 5] = bv; bwi[tid >> 5] = bi; bws[tid >> 5] = bs; }
        __syncthreads();
        if (tid == 0) {
            float fv = bwv[0]; int fi = bwi[0]; int fs = bws[0];
            #pragma unroll
            for (int w = 1; w < 8; w++) {
                if (bwv[w] > fv || (bwv[w] == fv && bwi[w] < fi)) {
                    fv = bwv[w]; fi = bwi[w]; fs = bws[w];
                }
            }
            out[q * TOPK + k] = fv;
            if (out_size >= 2 * BATCH * TOPK)
                out[BATCH * TOPK + q * TOPK + k] = (float)fi;
            v[fs] = -FLT_MAX;   // invalidate chosen slot
        }
        __syncthreads();
    }
}

// ---------------- launch ----------------
extern "C" void kernel_launch(void* const* d_in, const int* in_sizes, int n_in,
                              void* d_out, int out_size) {
    const float* query = (const float*)d_in[0];
    const float* emb   = (const float*)d_in[1];
    const float* dual  = (const float*)d_in[2];
    float* out = (float*)d_out;

    norm_q_kernel<<<BATCH, 128>>>(query);

    dim3 grid(BTILES, NCHUNKS);
    score_kernel<<<grid, 256>>>(emb, dual);

    merge_kernel<<<BATCH, 256>>>(out, out_size);
}